// round 7
// baseline (speedup 1.0000x reference)
#include <cuda_runtime.h>
#include <cuda_bf16.h>
#include <cstdint>

#define N_NODES 50000
#define N_EDGES 800000
#define TWO_N   100000
#define TWO_E   1600000
#define SCAN_BLK 1024
#define SCAN_NBLK ((TWO_N + SCAN_BLK - 1) / SCAN_BLK)   // 98

// ---------------- scratch ----------------------------------------------------
__device__ __align__(16) float g_xw[N_NODES * 256];   // x @ [W0 | W1]
__device__ __align__(16) float g_att[N_NODES * 32];   // [s0(8) d0(8) s1(8) d1(8)]
__device__ __align__(16) __nv_bfloat16 g_Whi[256 * 256];  // [k][n] n: [W0|W1]
__device__ __align__(16) __nv_bfloat16 g_Wlo[256 * 256];
__device__ int   g_deg[TWO_N];
__device__ int   g_off[TWO_N + 1];
__device__ int   g_cur[TWO_N];
__device__ int   g_srcarr[TWO_E];
__device__ int   g_bsum[SCAN_NBLK];
__device__ int   g_bsum_scan[SCAN_NBLK];

__device__ __forceinline__ uint32_t smem_u32(const void* p) {
    uint32_t a;
    asm("{ .reg .u64 t; cvta.to.shared.u64 t, %1; cvt.u32.u64 %0, t; }"
        : "=r"(a) : "l"(p));
    return a;
}

// ---------------- W split kernel ---------------------------------------------
__global__ void wsplit_kernel(const float* __restrict__ W0,
                              const float* __restrict__ W1) {
    int i = blockIdx.x * 256 + threadIdx.x;      // over [k][n], n in [0,256)
    int k = i >> 8, n = i & 255;
    float v = (n < 128) ? W0[k * 128 + n] : W1[k * 128 + (n - 128)];
    __nv_bfloat16 h = __float2bfloat16(v);
    g_Whi[i] = h;
    g_Wlo[i] = __float2bfloat16(v - __bfloat162float(h));
}

// ---------------- HMMA GEMM (split-bf16, 3 terms) + logits epilogue ----------
#define APAD 40
#define BPAD 136

__global__ __launch_bounds__(256) void gemm_hmma_kernel(
        const float* __restrict__ x,
        const float* __restrict__ as0, const float* __restrict__ ad0,
        const float* __restrict__ as1, const float* __restrict__ ad1) {
    __shared__ __nv_bfloat16 sAh[128][APAD];
    __shared__ __nv_bfloat16 sAl[128][APAD];
    __shared__ __nv_bfloat16 sBh[32][BPAD];
    __shared__ __nv_bfloat16 sBl[32][BPAD];

    int tid  = threadIdx.x;
    int wid  = tid >> 5;
    int lane = tid & 31;
    int m0   = blockIdx.x * 128;
    int half = blockIdx.y;
    int m0w  = (wid >> 1) * 32;
    int n0w  = (wid & 1) * 64;

    float acc[2][8][4];
#pragma unroll
    for (int a = 0; a < 2; a++)
#pragma unroll
        for (int b = 0; b < 8; b++)
#pragma unroll
            for (int c = 0; c < 4; c++) acc[a][b][c] = 0.f;

    int arow = tid >> 1, akb = (tid & 1) * 16;
    bool aok = (m0 + arow) < N_NODES;
    int bk = tid >> 3, bnb = (tid & 7) * 16;

    int a_roff = ((lane >> 3) & 1) * 8 + (lane & 7);
    int a_coff = ((lane >> 4) & 1) * 8;
    int b_koff = ((lane >> 3) & 1) * 8 + (lane & 7);
    int b_noff = ((lane >> 4) & 1) * 8;

    for (int kc = 0; kc < 8; kc++) {
        if (kc > 0) __syncthreads();
        {
            const float* src = x + (size_t)(m0 + arow) * 256 + kc * 32 + akb;
#pragma unroll
            for (int i = 0; i < 16; i += 4) {
                float4 v = aok ? *(const float4*)(src + i)
                               : make_float4(0.f, 0.f, 0.f, 0.f);
                float fv[4] = {v.x, v.y, v.z, v.w};
                uint32_t ph[2], pl[2];
#pragma unroll
                for (int j = 0; j < 2; j++) {
                    __nv_bfloat16 h0 = __float2bfloat16(fv[2*j]);
                    __nv_bfloat16 h1 = __float2bfloat16(fv[2*j+1]);
                    __nv_bfloat16 l0 = __float2bfloat16(fv[2*j]   - __bfloat162float(h0));
                    __nv_bfloat16 l1 = __float2bfloat16(fv[2*j+1] - __bfloat162float(h1));
                    ph[j] = (uint32_t)__bfloat16_as_ushort(h0)
                          | ((uint32_t)__bfloat16_as_ushort(h1) << 16);
                    pl[j] = (uint32_t)__bfloat16_as_ushort(l0)
                          | ((uint32_t)__bfloat16_as_ushort(l1) << 16);
                }
                *(uint2*)&sAh[arow][akb + i] = make_uint2(ph[0], ph[1]);
                *(uint2*)&sAl[arow][akb + i] = make_uint2(pl[0], pl[1]);
            }
        }
        {
            const __nv_bfloat16* wh = g_Whi + (size_t)(kc * 32 + bk) * 256 + half * 128 + bnb;
            const __nv_bfloat16* wl = g_Wlo + (size_t)(kc * 32 + bk) * 256 + half * 128 + bnb;
            uint4 vh0 = *(const uint4*)wh;
            uint4 vh1 = *(const uint4*)(wh + 8);
            uint4 vl0 = *(const uint4*)wl;
            uint4 vl1 = *(const uint4*)(wl + 8);
            *(uint4*)&sBh[bk][bnb]     = vh0;
            *(uint4*)&sBh[bk][bnb + 8] = vh1;
            *(uint4*)&sBl[bk][bnb]     = vl0;
            *(uint4*)&sBl[bk][bnb + 8] = vl1;
        }
        __syncthreads();

#pragma unroll
        for (int ks = 0; ks < 2; ks++) {
            int k0 = ks * 16;
            uint32_t ah[2][4], al[2][4], bb[4][4];
#pragma unroll
            for (int mt = 0; mt < 2; mt++) {
                uint32_t adrh = smem_u32(&sAh[m0w + mt * 16 + a_roff][k0 + a_coff]);
                asm volatile("ldmatrix.sync.aligned.m8n8.x4.shared.b16 {%0,%1,%2,%3}, [%4];"
                    : "=r"(ah[mt][0]), "=r"(ah[mt][1]), "=r"(ah[mt][2]), "=r"(ah[mt][3])
                    : "r"(adrh));
                uint32_t adrl = smem_u32(&sAl[m0w + mt * 16 + a_roff][k0 + a_coff]);
                asm volatile("ldmatrix.sync.aligned.m8n8.x4.shared.b16 {%0,%1,%2,%3}, [%4];"
                    : "=r"(al[mt][0]), "=r"(al[mt][1]), "=r"(al[mt][2]), "=r"(al[mt][3])
                    : "r"(adrl));
            }
#pragma unroll
            for (int p = 0; p < 4; p++) {
                uint32_t adr = smem_u32(&sBh[k0 + b_koff][n0w + p * 16 + b_noff]);
                asm volatile("ldmatrix.sync.aligned.m8n8.x4.trans.shared.b16 {%0,%1,%2,%3}, [%4];"
                    : "=r"(bb[p][0]), "=r"(bb[p][1]), "=r"(bb[p][2]), "=r"(bb[p][3])
                    : "r"(adr));
            }
#pragma unroll
            for (int mt = 0; mt < 2; mt++)
#pragma unroll
                for (int nt = 0; nt < 8; nt++) {
                    uint32_t b0 = bb[nt >> 1][(nt & 1) * 2];
                    uint32_t b1 = bb[nt >> 1][(nt & 1) * 2 + 1];
                    float* d = acc[mt][nt];
                    asm volatile(
                        "mma.sync.aligned.m16n8k16.row.col.f32.bf16.bf16.f32 "
                        "{%0,%1,%2,%3}, {%4,%5,%6,%7}, {%8,%9}, {%0,%1,%2,%3};"
                        : "+f"(d[0]), "+f"(d[1]), "+f"(d[2]), "+f"(d[3])
                        : "r"(ah[mt][0]), "r"(ah[mt][1]), "r"(ah[mt][2]), "r"(ah[mt][3]),
                          "r"(b0), "r"(b1));
                    asm volatile(
                        "mma.sync.aligned.m16n8k16.row.col.f32.bf16.bf16.f32 "
                        "{%0,%1,%2,%3}, {%4,%5,%6,%7}, {%8,%9}, {%0,%1,%2,%3};"
                        : "+f"(d[0]), "+f"(d[1]), "+f"(d[2]), "+f"(d[3])
                        : "r"(al[mt][0]), "r"(al[mt][1]), "r"(al[mt][2]), "r"(al[mt][3]),
                          "r"(b0), "r"(b1));
                }
#pragma unroll
            for (int p = 0; p < 4; p++) {
                uint32_t adr = smem_u32(&sBl[k0 + b_koff][n0w + p * 16 + b_noff]);
                asm volatile("ldmatrix.sync.aligned.m8n8.x4.trans.shared.b16 {%0,%1,%2,%3}, [%4];"
                    : "=r"(bb[p][0]), "=r"(bb[p][1]), "=r"(bb[p][2]), "=r"(bb[p][3])
                    : "r"(adr));
            }
#pragma unroll
            for (int mt = 0; mt < 2; mt++)
#pragma unroll
                for (int nt = 0; nt < 8; nt++) {
                    uint32_t b0 = bb[nt >> 1][(nt & 1) * 2];
                    uint32_t b1 = bb[nt >> 1][(nt & 1) * 2 + 1];
                    float* d = acc[mt][nt];
                    asm volatile(
                        "mma.sync.aligned.m16n8k16.row.col.f32.bf16.bf16.f32 "
                        "{%0,%1,%2,%3}, {%4,%5,%6,%7}, {%8,%9}, {%0,%1,%2,%3};"
                        : "+f"(d[0]), "+f"(d[1]), "+f"(d[2]), "+f"(d[3])
                        : "r"(ah[mt][0]), "r"(ah[mt][1]), "r"(ah[mt][2]), "r"(ah[mt][3]),
                          "r"(b0), "r"(b1));
                }
        }
    }

    // ---- epilogue: store xw + attention logits ----
#pragma unroll
    for (int mt = 0; mt < 2; mt++) {
        int r0 = m0 + m0w + mt * 16 + (lane >> 2);
        int r1 = r0 + 8;
        bool ok0 = r0 < N_NODES, ok1 = r1 < N_NODES;
#pragma unroll
        for (int nt = 0; nt < 8; nt++) {
            int col = half * 128 + n0w + nt * 8 + (lane & 3) * 2;
            if (ok0) *(float2*)&g_xw[(size_t)r0 * 256 + col] =
                make_float2(acc[mt][nt][0], acc[mt][nt][1]);
            if (ok1) *(float2*)&g_xw[(size_t)r1 * 256 + col] =
                make_float2(acc[mt][nt][2], acc[mt][nt][3]);
        }
    }

    const float* asv = half ? as1 : as0;
    const float* adv = half ? ad1 : ad0;
    float asr[16], adr_[16];
#pragma unroll
    for (int nt = 0; nt < 8; nt++) {
        int c = n0w + nt * 8 + (lane & 3) * 2;
        asr[nt * 2]     = asv[c];
        asr[nt * 2 + 1] = asv[c + 1];
        adr_[nt * 2]     = adv[c];
        adr_[nt * 2 + 1] = adv[c + 1];
    }
#pragma unroll
    for (int mt = 0; mt < 2; mt++) {
#pragma unroll
        for (int rh = 0; rh < 2; rh++) {
            float ps[4] = {0.f, 0.f, 0.f, 0.f};
            float pd[4] = {0.f, 0.f, 0.f, 0.f};
#pragma unroll
            for (int nt = 0; nt < 8; nt++) {
                int h = nt >> 1;
                float a0 = acc[mt][nt][rh * 2];
                float a1 = acc[mt][nt][rh * 2 + 1];
                ps[h] += a0 * asr[nt * 2] + a1 * asr[nt * 2 + 1];
                pd[h] += a0 * adr_[nt * 2] + a1 * adr_[nt * 2 + 1];
            }
#pragma unroll
            for (int off = 1; off < 4; off <<= 1) {
#pragma unroll
                for (int h = 0; h < 4; h++) {
                    ps[h] += __shfl_xor_sync(0xffffffffu, ps[h], off);
                    pd[h] += __shfl_xor_sync(0xffffffffu, pd[h], off);
                }
            }
            int r = m0 + m0w + mt * 16 + rh * 8 + (lane >> 2);
            if ((lane & 3) == 0 && r < N_NODES) {
#pragma unroll
                for (int h = 0; h < 4; h++) {
                    int gh = (n0w >> 4) + h;
                    g_att[r * 32 + half * 16 + gh]     = ps[h];
                    g_att[r * 32 + half * 16 + 8 + gh] = pd[h];
                }
            }
        }
    }
}

// ---------------- zero degree counters ---------------------------------------
__global__ void zero_kernel() {
    int i = blockIdx.x * blockDim.x + threadIdx.x;
    if (i < TWO_N) g_deg[i] = 0;
}

// ---------------- count in-degrees, 4 edges/thread ---------------------------
__global__ void count_kernel(const int* __restrict__ row,
                             const int* __restrict__ col) {
    int base = (blockIdx.x * blockDim.x + threadIdx.x) * 4;
    int d0[4];
#pragma unroll
    for (int i = 0; i < 4; i++) {
        int e = base + i;
        d0[i] = (e < N_EDGES) ? col[e] : -1;
    }
#pragma unroll
    for (int i = 0; i < 4; i++)
        if (d0[i] >= 0) atomicAdd(&g_deg[d0[i]], 1);
    int d1[4];
#pragma unroll
    for (int i = 0; i < 4; i++) d1[i] = (d0[i] >= 0) ? col[d0[i]] : -1;
#pragma unroll
    for (int i = 0; i < 4; i++)
        if (d1[i] >= 0) atomicAdd(&g_deg[N_NODES + d1[i]], 1);
}

// ---------------- exclusive scan (3 stages) ----------------------------------
__global__ void scanA_kernel() {
    __shared__ int sh[SCAN_BLK];
    int t = threadIdx.x;
    int i = blockIdx.x * SCAN_BLK + t;
    int v = (i < TWO_N) ? g_deg[i] : 0;
    sh[t] = v;
    __syncthreads();
    for (int off = 1; off < SCAN_BLK; off <<= 1) {
        int add = (t >= off) ? sh[t - off] : 0;
        __syncthreads();
        sh[t] += add;
        __syncthreads();
    }
    if (i < TWO_N) g_off[i] = sh[t] - v;
    if (t == SCAN_BLK - 1) g_bsum[blockIdx.x] = sh[SCAN_BLK - 1];
}

__global__ void scanB_kernel() {
    __shared__ int sh[128];
    int t = threadIdx.x;
    int v = (t < SCAN_NBLK) ? g_bsum[t] : 0;
    sh[t] = v;
    __syncthreads();
    for (int off = 1; off < 128; off <<= 1) {
        int add = (t >= off) ? sh[t - off] : 0;
        __syncthreads();
        sh[t] += add;
        __syncthreads();
    }
    if (t < SCAN_NBLK) g_bsum_scan[t] = sh[t] - v;
}

__global__ void scanC_kernel() {
    int i = blockIdx.x * SCAN_BLK + threadIdx.x;
    if (i < TWO_N) {
        int v = g_off[i] + g_bsum_scan[blockIdx.x];
        g_off[i] = v;
        g_cur[i] = v;
    }
    if (i == 0) g_off[TWO_N] = TWO_E;
}

// ---------------- scatter into CSR, 4 edges/thread ---------------------------
__global__ void scatter_kernel(const int* __restrict__ row,
                               const int* __restrict__ col) {
    int base = (blockIdx.x * blockDim.x + threadIdx.x) * 4;
    int r0[4], d0[4];
#pragma unroll
    for (int i = 0; i < 4; i++) {
        int e = base + i;
        if (e < N_EDGES) { r0[i] = row[e]; d0[i] = col[e]; }
        else { r0[i] = -1; d0[i] = -1; }
    }
#pragma unroll
    for (int i = 0; i < 4; i++) {
        if (d0[i] >= 0) {
            int p = atomicAdd(&g_cur[d0[i]], 1);
            g_srcarr[p] = r0[i];
        }
    }
    int r1[4], d1[4];
#pragma unroll
    for (int i = 0; i < 4; i++) {
        if (d0[i] >= 0) { r1[i] = row[d0[i]]; d1[i] = col[d0[i]]; }
        else { r1[i] = -1; d1[i] = -1; }
    }
#pragma unroll
    for (int i = 0; i < 4; i++) {
        if (d1[i] >= 0) {
            int p = atomicAdd(&g_cur[N_NODES + d1[i]], 1);
            g_srcarr[p] = r1[i];
        }
    }
}

// ---------------- fused aggregation + residual + LayerNorm -------------------
// warp per (node, hop): block 256 = 4 nodes x 2 warps; LN joined via smem.
// 50000 nodes = 12500 blocks x 4 exactly (no bounds checks needed).
__global__ __launch_bounds__(256) void agg_ln_kernel(
        const float* __restrict__ b0, const float* __restrict__ b1,
        const float* __restrict__ x,
        const float* __restrict__ gamma, const float* __restrict__ beta,
        float* __restrict__ out) {
    __shared__ float s_s[4][2], s_s2[4][2];
    int wid  = threadIdx.x >> 5;
    int lane = threadIdx.x & 31;
    int nl   = wid >> 1;                 // node within block
    int hop  = wid & 1;
    int n    = blockIdx.x * 4 + nl;
    int head = lane >> 2;
    int c0   = lane * 4;

    float ad  = g_att[n * 32 + hop * 16 + 8 + head];
    float t   = g_att[n * 32 + hop * 16 + head] + ad;
    t = (t > 0.f) ? t : 0.2f * t;
    float p = __expf(t) * (hop ? 2.0f : 1.0f);   // hop-2 self loop appears twice
    float sum = p;
    float4 v = *(const float4*)&g_xw[n * 256 + hop * 128 + c0];
    float4 acc = make_float4(p * v.x, p * v.y, p * v.z, p * v.w);

    int gw = hop * N_NODES + n;
    int je = g_off[gw + 1];
    for (int j = g_off[gw]; j < je; j++) {
        int src = g_srcarr[j];
        float tt = g_att[src * 32 + hop * 16 + head] + ad;
        tt = (tt > 0.f) ? tt : 0.2f * tt;
        float pp = __expf(tt);
        sum += pp;
        float4 w = *(const float4*)&g_xw[src * 256 + hop * 128 + c0];
        acc.x += pp * w.x; acc.y += pp * w.y;
        acc.z += pp * w.z; acc.w += pp * w.w;
    }

    float inv = 1.f / sum;
    const float* bias = hop ? b1 : b0;
    float4 bb = *(const float4*)&bias[c0];
    float4 xr = *(const float4*)&x[n * 256 + hop * 128 + c0];
    float vv[4];
    vv[0] = acc.x * inv + bb.x + xr.x;
    vv[1] = acc.y * inv + bb.y + xr.y;
    vv[2] = acc.z * inv + bb.z + xr.z;
    vv[3] = acc.w * inv + bb.w + xr.w;

    float s = vv[0] + vv[1] + vv[2] + vv[3];
    float s2 = vv[0]*vv[0] + vv[1]*vv[1] + vv[2]*vv[2] + vv[3]*vv[3];
#pragma unroll
    for (int off = 16; off > 0; off >>= 1) {
        s  += __shfl_xor_sync(0xffffffffu, s, off);
        s2 += __shfl_xor_sync(0xffffffffu, s2, off);
    }
    if (lane == 0) { s_s[nl][hop] = s; s_s2[nl][hop] = s2; }
    __syncthreads();
    float ts  = s_s[nl][0] + s_s[nl][1];
    float ts2 = s_s2[nl][0] + s_s2[nl][1];
    float mean = ts * (1.f / 256.f);
    float var  = ts2 * (1.f / 256.f) - mean * mean;
    float rs   = rsqrtf(var + 1e-5f);

    float4 gm = *(const float4*)&gamma[hop * 128 + c0];
    float4 be = *(const float4*)&beta[hop * 128 + c0];
    float4 o;
    o.x = (vv[0] - mean) * rs * gm.x + be.x;
    o.y = (vv[1] - mean) * rs * gm.y + be.y;
    o.z = (vv[2] - mean) * rs * gm.z + be.z;
    o.w = (vv[3] - mean) * rs * gm.w + be.w;
    *(float4*)&out[n * 256 + hop * 128 + c0] = o;
}

// ---------------- launch -----------------------------------------------------
extern "C" void kernel_launch(void* const* d_in, const int* in_sizes, int n_in,
                              void* d_out, int out_size) {
    const float* x     = (const float*)d_in[0];
    const int*   ei    = (const int*)d_in[1];
    const float* W0    = (const float*)d_in[2];
    const float* as0   = (const float*)d_in[3];
    const float* ad0   = (const float*)d_in[4];
    const float* b0    = (const float*)d_in[5];
    const float* W1    = (const float*)d_in[6];
    const float* as1   = (const float*)d_in[7];
    const float* ad1   = (const float*)d_in[8];
    const float* b1    = (const float*)d_in[9];
    const float* gamma = (const float*)d_in[10];
    const float* beta  = (const float*)d_in[11];
    float* out = (float*)d_out;

    const int* row = ei;
    const int* col = ei + N_EDGES;

    static cudaStream_t s2 = nullptr;
    static cudaEvent_t evA = nullptr, evB = nullptr;
    if (s2 == nullptr) {
        cudaStreamCreateWithFlags(&s2, cudaStreamNonBlocking);
        cudaEventCreateWithFlags(&evA, cudaEventDisableTiming);
        cudaEventCreateWithFlags(&evB, cudaEventDisableTiming);
    }

    // fork: CSR chain on s2, GEMM chain on the capture (default) stream
    cudaEventRecord(evA, 0);
    cudaStreamWaitEvent(s2, evA, 0);

    zero_kernel<<<(TWO_N + 255) / 256, 256, 0, s2>>>();
    count_kernel<<<(N_EDGES / 4 + 255) / 256, 256, 0, s2>>>(row, col);
    scanA_kernel<<<SCAN_NBLK, SCAN_BLK, 0, s2>>>();
    scanB_kernel<<<1, 128, 0, s2>>>();
    scanC_kernel<<<SCAN_NBLK, SCAN_BLK, 0, s2>>>();
    scatter_kernel<<<(N_EDGES / 4 + 255) / 256, 256, 0, s2>>>(row, col);

    wsplit_kernel<<<256, 256>>>(W0, W1);
    gemm_hmma_kernel<<<dim3((N_NODES + 127) / 128, 2), 256>>>(x, as0, ad0, as1, ad1);

    // join
    cudaEventRecord(evB, s2);
    cudaStreamWaitEvent(0, evB, 0);

    agg_ln_kernel<<<N_NODES / 4, 256>>>(b0, b1, x, gamma, beta, out);
}